// round 4
// baseline (speedup 1.0000x reference)
#include <cuda_runtime.h>
#include <cuda_bf16.h>

// Output[b,s,:] == mean(knowledge, axis=0) for every (b,s):
// top_k with max_chunks == K selects a permutation of ALL knowledge rows,
// so mean(take(knowledge, top_k), axis=1) == mean(knowledge, axis=0).
//
// R1/R2 showed both scalar-STG and TMA broadcast kernels pin at ~5.6-5.9us
// with <15% of any pipe used: the measurement is launch-overhead dominated.
// So: ONE fused kernel. Each CTA recomputes the 512-float mean itself
// (knowledge is only 128KB -> L2-broadcast reads, ~free) and writes its
// slice of output rows. No inter-kernel dependency, no second launch.

#define E_DIM 512
#define K_ROWS 64
#define THREADS 128            // 128 threads * float4 = one 512-float row
#define ROWS_PER_CTA 16        // 4096 rows / 16 = 256 CTAs (~2 waves-worth idle-cheap)

__global__ void __launch_bounds__(THREADS)
fused_mean_broadcast(const float4* __restrict__ knowledge4,
                     float4* __restrict__ out, int rows) {
    int t = threadIdx.x;  // owns columns 4t..4t+3

    // Sum over the 64 knowledge rows. Fully unrolled -> deep MLP,
    // one exposed DRAM/L2 latency for the whole reduction.
    float4 s = make_float4(0.f, 0.f, 0.f, 0.f);
#pragma unroll
    for (int k = 0; k < K_ROWS; ++k) {
        float4 a = knowledge4[k * (E_DIM / 4) + t];
        s.x += a.x; s.y += a.y; s.z += a.z; s.w += a.w;
    }
    const float inv = 1.0f / (float)K_ROWS;
    s.x *= inv; s.y *= inv; s.z *= inv; s.w *= inv;

    // Write this CTA's contiguous block of identical rows.
    size_t base = (size_t)blockIdx.x * ROWS_PER_CTA * (E_DIM / 4) + t;
    int r0 = blockIdx.x * ROWS_PER_CTA;
    int n = min(ROWS_PER_CTA, rows - r0);
#pragma unroll
    for (int r = 0; r < ROWS_PER_CTA; ++r) {
        if (r < n) out[base + (size_t)r * (E_DIM / 4)] = s;
    }
}

extern "C" void kernel_launch(void* const* d_in, const int* in_sizes, int n_in,
                              void* d_out, int out_size) {
    // d_in[0]: query_embedding [4,1024,512] f32 (unused — output is query-independent)
    // d_in[1]: knowledge [64,512] f32
    const float* knowledge = (const float*)d_in[1];
    float* out = (float*)d_out;

    int rows = out_size / E_DIM;                          // 4096
    int blocks = (rows + ROWS_PER_CTA - 1) / ROWS_PER_CTA; // 256

    fused_mean_broadcast<<<blocks, THREADS>>>(
        reinterpret_cast<const float4*>(knowledge),
        reinterpret_cast<float4*>(out), rows);
}